// round 14
// baseline (speedup 1.0000x reference)
#include <cuda_runtime.h>
#include <cuda_bf16.h>
#include <stdint.h>

// ---------------------------------------------------------------------------
// GCN layer: out = scatter_sum(y[src] -> dst) + bias, where y = x @ W^T
// Inputs (int64 tensors arrive as int32 per harness dtype mapping):
//   0: x float32 [N,64]  1: W float32 [64,64]  2: bias float32 [64]
//   3: edge_index int32 [2,E]  4..6: unused hints
// Output: float32 [N, 64]
//
// Pipeline (consolidated best-of-measured):
//   1) cudaMemsetAsync : reset CSR degree + overflow counters
//   2) fused_gemm_build: blocks [0,Gg) = GEMM tiles (scalar 4x4 register
//                        tile, the fastest measured variant);
//                        blocks [Gg,..) = CSR build (edge -> dst slot).
//   3) gather_csr      : per-dst accumulate from L2-resident y (+bias),
//                        4-way unroll, no atomics; overflow fixup folded in
//                        via one broadcast scalar (normally zero work).
// ---------------------------------------------------------------------------

#define D 64
#define MAX_N 100000
#define CAP 64
#define OVF_MAX 8192

__device__ __align__(16) float g_y[(size_t)MAX_N * D];
__device__ int g_deg[MAX_N];
__device__ int g_adj[(size_t)MAX_N * CAP];
__device__ int g_ovf_cnt;
__device__ int g_ovf[OVF_MAX];

// ---------------------------------------------------------------------------
// Fused GEMM + CSR build (concatenated roles).
// ---------------------------------------------------------------------------
__global__ __launch_bounds__(256) void fused_gemm_build(
    const float* __restrict__ x, const float* __restrict__ W,
    float* __restrict__ y, int N,
    const int* __restrict__ ei, int E, int gemmBlocks)
{
    const int tid = threadIdx.x;

    if (blockIdx.x >= gemmBlocks) {
        // ----- CSR build branch -----
        int e = (blockIdx.x - gemmBlocks) * 256 + tid;
        if (e >= E) return;
        int src = __ldg(&ei[e]);
        int dst = __ldg(&ei[E + e]);
        if (((unsigned)src >= (unsigned)N) | ((unsigned)dst >= (unsigned)N)) return;
        int pos = atomicAdd(&g_deg[dst], 1);
        if (pos < CAP) {
            g_adj[(size_t)dst * CAP + pos] = src;
        } else {
            int i = atomicAdd(&g_ovf_cnt, 1);
            if (i < OVF_MAX) g_ovf[i] = e;
        }
        return;
    }

    // ----- GEMM branch: y = x @ W^T (scalar 4x4 register tile) -----
    __shared__ float sWt[D][D + 4];   // sWt[k][o] = W[o][k]
    __shared__ float sx[64][D];

    #pragma unroll
    for (int i = tid; i < D * D; i += 256)
        sWt[i & 63][i >> 6] = W[i];

    const int row0 = blockIdx.x * 64;
    #pragma unroll
    for (int it = 0; it < 4; it++) {
        int j = tid + it * 256;          // 0..1023 float4 slots
        int r = j >> 4, c4 = j & 15;
        int row = row0 + r;
        float4 v = make_float4(0.f, 0.f, 0.f, 0.f);
        if (row < N) v = reinterpret_cast<const float4*>(x)[(size_t)row * 16 + c4];
        reinterpret_cast<float4*>(&sx[r][0])[c4] = v;
    }
    __syncthreads();

    const int tx = tid & 15;
    const int ty = tid >> 4;

    float4 a0 = make_float4(0.f,0.f,0.f,0.f);
    float4 a1 = a0, a2 = a0, a3 = a0;

    #pragma unroll 8
    for (int k = 0; k < D; k++) {
        float4 w = *reinterpret_cast<const float4*>(&sWt[k][tx * 4]);
        float x0 = sx[ty      ][k];
        float x1 = sx[ty + 16][k];
        float x2 = sx[ty + 32][k];
        float x3 = sx[ty + 48][k];
        a0.x = fmaf(x0, w.x, a0.x); a0.y = fmaf(x0, w.y, a0.y);
        a0.z = fmaf(x0, w.z, a0.z); a0.w = fmaf(x0, w.w, a0.w);
        a1.x = fmaf(x1, w.x, a1.x); a1.y = fmaf(x1, w.y, a1.y);
        a1.z = fmaf(x1, w.z, a1.z); a1.w = fmaf(x1, w.w, a1.w);
        a2.x = fmaf(x2, w.x, a2.x); a2.y = fmaf(x2, w.y, a2.y);
        a2.z = fmaf(x2, w.z, a2.z); a2.w = fmaf(x2, w.w, a2.w);
        a3.x = fmaf(x3, w.x, a3.x); a3.y = fmaf(x3, w.y, a3.y);
        a3.z = fmaf(x3, w.z, a3.z); a3.w = fmaf(x3, w.w, a3.w);
    }

    float4* y4 = reinterpret_cast<float4*>(y);
    int r0 = row0 + ty;
    if (r0      < N) y4[(size_t)(r0      ) * 16 + tx] = a0;
    if (r0 + 16 < N) y4[(size_t)(r0 + 16) * 16 + tx] = a1;
    if (r0 + 32 < N) y4[(size_t)(r0 + 32) * 16 + tx] = a2;
    if (r0 + 48 < N) y4[(size_t)(r0 + 48) * 16 + tx] = a3;
}

// ---------------------------------------------------------------------------
// Gather: 16 threads per dst (thread c owns float4 chunk c). Single write per
// output row, bias folded in, no atomics. 4-way unroll (MLP=4). Overflow
// fixup folded in (one broadcast scalar load; normally zero iterations).
// ---------------------------------------------------------------------------
__global__ __launch_bounds__(256) void gather_csr(
    const float* __restrict__ bias, float* __restrict__ out, int N,
    const int* __restrict__ ei, int E)
{
    int d = blockIdx.x * 16 + (threadIdx.x >> 4);
    int c = threadIdx.x & 15;
    if (d >= N) return;

    int cnt = g_deg[d];
    if (cnt > CAP) cnt = CAP;

    float4 acc = __ldg(reinterpret_cast<const float4*>(bias) + c);
    const int* lst = &g_adj[(size_t)d * CAP];
    const float4* y4 = reinterpret_cast<const float4*>(g_y);

    float4 acc2 = make_float4(0.f, 0.f, 0.f, 0.f);
    int i = 0;
    for (; i + 4 <= cnt; i += 4) {
        int s0 = __ldg(&lst[i]);
        int s1 = __ldg(&lst[i + 1]);
        int s2 = __ldg(&lst[i + 2]);
        int s3 = __ldg(&lst[i + 3]);
        float4 v0 = __ldg(y4 + (size_t)s0 * 16 + c);
        float4 v1 = __ldg(y4 + (size_t)s1 * 16 + c);
        float4 v2 = __ldg(y4 + (size_t)s2 * 16 + c);
        float4 v3 = __ldg(y4 + (size_t)s3 * 16 + c);
        acc.x  += v0.x; acc.y  += v0.y; acc.z  += v0.z; acc.w  += v0.w;
        acc2.x += v1.x; acc2.y += v1.y; acc2.z += v1.z; acc2.w += v1.w;
        acc.x  += v2.x; acc.y  += v2.y; acc.z  += v2.z; acc.w  += v2.w;
        acc2.x += v3.x; acc2.y += v3.y; acc2.z += v3.z; acc2.w += v3.w;
    }
    for (; i < cnt; i++) {
        int s0 = __ldg(&lst[i]);
        float4 v0 = __ldg(y4 + (size_t)s0 * 16 + c);
        acc.x += v0.x; acc.y += v0.y; acc.z += v0.z; acc.w += v0.w;
    }
    acc.x += acc2.x; acc.y += acc2.y; acc.z += acc2.z; acc.w += acc2.w;

    // Overflow fixup: one broadcast scalar load; loop dead for Poisson(16).
    int ovf = g_ovf_cnt;
    if (ovf > 0) {
        if (ovf > OVF_MAX) ovf = OVF_MAX;
        for (int j = 0; j < ovf; j++) {
            int e = g_ovf[j];
            if (__ldg(&ei[E + e]) != d) continue;
            int s = __ldg(&ei[e]);
            float4 v = __ldg(y4 + (size_t)s * 16 + c);
            acc.x += v.x; acc.y += v.y; acc.z += v.z; acc.w += v.w;
        }
    }

    reinterpret_cast<float4*>(out)[(size_t)d * 16 + c] = acc;
}

// ---------------------------------------------------------------------------
extern "C" void kernel_launch(void* const* d_in, const int* in_sizes, int n_in,
                              void* d_out, int out_size)
{
    const float* x    = (const float*)d_in[0];
    const float* W    = (const float*)d_in[1];
    const float* bias = (const float*)d_in[2];
    const int*   ei   = (const int*)d_in[3];

    const int N = in_sizes[0] / D;
    const int E = in_sizes[3] / 2;
    float* out = (float*)d_out;

    float* y;    cudaGetSymbolAddress((void**)&y, g_y);
    void* degp;  cudaGetSymbolAddress(&degp, g_deg);
    void* ovfp;  cudaGetSymbolAddress(&ovfp, g_ovf_cnt);

    // 1) reset counters (graph-capturable memset nodes)
    cudaMemsetAsync(degp, 0, (size_t)N * sizeof(int));
    cudaMemsetAsync(ovfp, 0, sizeof(int));

    // 2) fused GEMM + CSR build
    const int gemmBlocks  = (N + 63) / 64;
    const int buildBlocks = (E + 255) / 256;
    fused_gemm_build<<<gemmBlocks + buildBlocks, 256>>>(x, W, y, N, ei, E, gemmBlocks);

    // 3) dst-centric accumulate (+bias, +overflow fixup)
    gather_csr<<<(N + 15) / 16, 256>>>(bias, out, N, ei, E);
}

// round 15
// speedup vs baseline: 1.0063x; 1.0063x over previous
#include <cuda_runtime.h>
#include <cuda_bf16.h>
#include <stdint.h>

// ---------------------------------------------------------------------------
// GCN layer: out = scatter_sum(y[src] -> dst) + bias, where y = x @ W^T
// Inputs (int64 tensors arrive as int32 per harness dtype mapping):
//   0: x float32 [N,64]  1: W float32 [64,64]  2: bias float32 [64]
//   3: edge_index int32 [2,E]  4..6: unused hints
// Output: float32 [N, 64]
//
// Pipeline (consolidated best-of-measured):
//   1) cudaMemsetAsync : reset CSR degree + overflow counters
//   2) fused_gemm_build: blocks [0,Gg) = GEMM tiles (scalar 4x4 register
//                        tile, the fastest measured variant);
//                        blocks [Gg,..) = CSR build (edge -> dst slot).
//   3) gather_csr      : per-dst accumulate from L2-resident y (+bias),
//                        4-way unroll, no atomics; overflow fixup folded in
//                        via one broadcast scalar (normally zero work).
// ---------------------------------------------------------------------------

#define D 64
#define MAX_N 100000
#define CAP 64
#define OVF_MAX 8192

__device__ __align__(16) float g_y[(size_t)MAX_N * D];
__device__ int g_deg[MAX_N];
__device__ int g_adj[(size_t)MAX_N * CAP];
__device__ int g_ovf_cnt;
__device__ int g_ovf[OVF_MAX];

// ---------------------------------------------------------------------------
// Fused GEMM + CSR build (concatenated roles).
// ---------------------------------------------------------------------------
__global__ __launch_bounds__(256) void fused_gemm_build(
    const float* __restrict__ x, const float* __restrict__ W,
    float* __restrict__ y, int N,
    const int* __restrict__ ei, int E, int gemmBlocks)
{
    const int tid = threadIdx.x;

    if (blockIdx.x >= gemmBlocks) {
        // ----- CSR build branch -----
        int e = (blockIdx.x - gemmBlocks) * 256 + tid;
        if (e >= E) return;
        int src = __ldg(&ei[e]);
        int dst = __ldg(&ei[E + e]);
        if (((unsigned)src >= (unsigned)N) | ((unsigned)dst >= (unsigned)N)) return;
        int pos = atomicAdd(&g_deg[dst], 1);
        if (pos < CAP) {
            g_adj[(size_t)dst * CAP + pos] = src;
        } else {
            int i = atomicAdd(&g_ovf_cnt, 1);
            if (i < OVF_MAX) g_ovf[i] = e;
        }
        return;
    }

    // ----- GEMM branch: y = x @ W^T (scalar 4x4 register tile) -----
    __shared__ float sWt[D][D + 4];   // sWt[k][o] = W[o][k]
    __shared__ float sx[64][D];

    #pragma unroll
    for (int i = tid; i < D * D; i += 256)
        sWt[i & 63][i >> 6] = W[i];

    const int row0 = blockIdx.x * 64;
    #pragma unroll
    for (int it = 0; it < 4; it++) {
        int j = tid + it * 256;          // 0..1023 float4 slots
        int r = j >> 4, c4 = j & 15;
        int row = row0 + r;
        float4 v = make_float4(0.f, 0.f, 0.f, 0.f);
        if (row < N) v = reinterpret_cast<const float4*>(x)[(size_t)row * 16 + c4];
        reinterpret_cast<float4*>(&sx[r][0])[c4] = v;
    }
    __syncthreads();

    const int tx = tid & 15;
    const int ty = tid >> 4;

    float4 a0 = make_float4(0.f,0.f,0.f,0.f);
    float4 a1 = a0, a2 = a0, a3 = a0;

    #pragma unroll 8
    for (int k = 0; k < D; k++) {
        float4 w = *reinterpret_cast<const float4*>(&sWt[k][tx * 4]);
        float x0 = sx[ty      ][k];
        float x1 = sx[ty + 16][k];
        float x2 = sx[ty + 32][k];
        float x3 = sx[ty + 48][k];
        a0.x = fmaf(x0, w.x, a0.x); a0.y = fmaf(x0, w.y, a0.y);
        a0.z = fmaf(x0, w.z, a0.z); a0.w = fmaf(x0, w.w, a0.w);
        a1.x = fmaf(x1, w.x, a1.x); a1.y = fmaf(x1, w.y, a1.y);
        a1.z = fmaf(x1, w.z, a1.z); a1.w = fmaf(x1, w.w, a1.w);
        a2.x = fmaf(x2, w.x, a2.x); a2.y = fmaf(x2, w.y, a2.y);
        a2.z = fmaf(x2, w.z, a2.z); a2.w = fmaf(x2, w.w, a2.w);
        a3.x = fmaf(x3, w.x, a3.x); a3.y = fmaf(x3, w.y, a3.y);
        a3.z = fmaf(x3, w.z, a3.z); a3.w = fmaf(x3, w.w, a3.w);
    }

    float4* y4 = reinterpret_cast<float4*>(y);
    int r0 = row0 + ty;
    if (r0      < N) y4[(size_t)(r0      ) * 16 + tx] = a0;
    if (r0 + 16 < N) y4[(size_t)(r0 + 16) * 16 + tx] = a1;
    if (r0 + 32 < N) y4[(size_t)(r0 + 32) * 16 + tx] = a2;
    if (r0 + 48 < N) y4[(size_t)(r0 + 48) * 16 + tx] = a3;
}

// ---------------------------------------------------------------------------
// Gather: 16 threads per dst (thread c owns float4 chunk c). Single write per
// output row, bias folded in, no atomics. 4-way unroll (MLP=4). Overflow
// fixup folded in (one broadcast scalar load; normally zero iterations).
// ---------------------------------------------------------------------------
__global__ __launch_bounds__(256) void gather_csr(
    const float* __restrict__ bias, float* __restrict__ out, int N,
    const int* __restrict__ ei, int E)
{
    int d = blockIdx.x * 16 + (threadIdx.x >> 4);
    int c = threadIdx.x & 15;
    if (d >= N) return;

    int cnt = g_deg[d];
    if (cnt > CAP) cnt = CAP;

    float4 acc = __ldg(reinterpret_cast<const float4*>(bias) + c);
    const int* lst = &g_adj[(size_t)d * CAP];
    const float4* y4 = reinterpret_cast<const float4*>(g_y);

    float4 acc2 = make_float4(0.f, 0.f, 0.f, 0.f);
    int i = 0;
    for (; i + 4 <= cnt; i += 4) {
        int s0 = __ldg(&lst[i]);
        int s1 = __ldg(&lst[i + 1]);
        int s2 = __ldg(&lst[i + 2]);
        int s3 = __ldg(&lst[i + 3]);
        float4 v0 = __ldg(y4 + (size_t)s0 * 16 + c);
        float4 v1 = __ldg(y4 + (size_t)s1 * 16 + c);
        float4 v2 = __ldg(y4 + (size_t)s2 * 16 + c);
        float4 v3 = __ldg(y4 + (size_t)s3 * 16 + c);
        acc.x  += v0.x; acc.y  += v0.y; acc.z  += v0.z; acc.w  += v0.w;
        acc2.x += v1.x; acc2.y += v1.y; acc2.z += v1.z; acc2.w += v1.w;
        acc.x  += v2.x; acc.y  += v2.y; acc.z  += v2.z; acc.w  += v2.w;
        acc2.x += v3.x; acc2.y += v3.y; acc2.z += v3.z; acc2.w += v3.w;
    }
    for (; i < cnt; i++) {
        int s0 = __ldg(&lst[i]);
        float4 v0 = __ldg(y4 + (size_t)s0 * 16 + c);
        acc.x += v0.x; acc.y += v0.y; acc.z += v0.z; acc.w += v0.w;
    }
    acc.x += acc2.x; acc.y += acc2.y; acc.z += acc2.z; acc.w += acc2.w;

    // Overflow fixup: one broadcast scalar load; loop dead for Poisson(16).
    int ovf = g_ovf_cnt;
    if (ovf > 0) {
        if (ovf > OVF_MAX) ovf = OVF_MAX;
        for (int j = 0; j < ovf; j++) {
            int e = g_ovf[j];
            if (__ldg(&ei[E + e]) != d) continue;
            int s = __ldg(&ei[e]);
            float4 v = __ldg(y4 + (size_t)s * 16 + c);
            acc.x += v.x; acc.y += v.y; acc.z += v.z; acc.w += v.w;
        }
    }

    reinterpret_cast<float4*>(out)[(size_t)d * 16 + c] = acc;
}

// ---------------------------------------------------------------------------
extern "C" void kernel_launch(void* const* d_in, const int* in_sizes, int n_in,
                              void* d_out, int out_size)
{
    const float* x    = (const float*)d_in[0];
    const float* W    = (const float*)d_in[1];
    const float* bias = (const float*)d_in[2];
    const int*   ei   = (const int*)d_in[3];

    const int N = in_sizes[0] / D;
    const int E = in_sizes[3] / 2;
    float* out = (float*)d_out;

    float* y;    cudaGetSymbolAddress((void**)&y, g_y);
    void* degp;  cudaGetSymbolAddress(&degp, g_deg);
    void* ovfp;  cudaGetSymbolAddress(&ovfp, g_ovf_cnt);

    // 1) reset counters (graph-capturable memset nodes)
    cudaMemsetAsync(degp, 0, (size_t)N * sizeof(int));
    cudaMemsetAsync(ovfp, 0, sizeof(int));

    // 2) fused GEMM + CSR build
    const int gemmBlocks  = (N + 63) / 64;
    const int buildBlocks = (E + 255) / 256;
    fused_gemm_build<<<gemmBlocks + buildBlocks, 256>>>(x, W, y, N, ei, E, gemmBlocks);

    // 3) dst-centric accumulate (+bias, +overflow fixup)
    gather_csr<<<(N + 15) / 16, 256>>>(bias, out, N, ei, E);
}